// round 1
// baseline (speedup 1.0000x reference)
#include <cuda_runtime.h>
#include <math.h>

#define NN   8192
#define FDIM 512
#define NE   262144
#define NF   (NN * FDIM)   // 4194304

// ---------------------------------------------------------------------------
// Static device scratch (no allocations allowed)
// ---------------------------------------------------------------------------
__device__ float g_feat[NF];
__device__ float g_h[NF];
__device__ float g_ys1[NF];
__device__ float g_yg1[NF];
__device__ float g_mp1[NF];
__device__ float g_ys2[NF];
__device__ float g_yg2[NF];
__device__ float g_dinv_s[NN];
__device__ float g_dinv_g[NN];
__device__ float g_dinv_I[NN];
__device__ float g_coef_s[NE];
__device__ float g_coef_g[NE];
__device__ float g_coef_I[NE];
__device__ float g_pooled[4];
__device__ float g_att[4];

// ---------------------------------------------------------------------------
// Small utility kernels
// ---------------------------------------------------------------------------
__global__ void fill_kernel(float* p, float v, int n) {
    int i = blockIdx.x * blockDim.x + threadIdx.x;
    if (i < n) p[i] = v;
}

__global__ void deg_kernel(const int* __restrict__ dst, const float* __restrict__ w,
                           float* __restrict__ deg) {
    int e = blockIdx.x * blockDim.x + threadIdx.x;
    if (e < NE) atomicAdd(&deg[dst[e]], w ? w[e] : 1.0f);
}

__global__ void rsqrt_kernel(float* p, int n) {
    int i = blockIdx.x * blockDim.x + threadIdx.x;
    if (i < n) p[i] = rsqrtf(p[i]);   // deg >= 1 always (self loop)
}

__global__ void coef_kernel(const int* __restrict__ src, const int* __restrict__ dst,
                            const float* __restrict__ w, const float* __restrict__ dinv,
                            float* __restrict__ coef) {
    int e = blockIdx.x * blockDim.x + threadIdx.x;
    if (e < NE) coef[e] = dinv[src[e]] * (w ? w[e] : 1.0f) * dinv[dst[e]];
}

// ---------------------------------------------------------------------------
// SGEMM: C[M,Nc] = A[M,K] @ B[K,Nc] (+ bias broadcast over rows, optional)
// BM=128, BN=64, BK=16, 256 threads, 8x4 per thread.
// All dims here are multiples of tile sizes (M in {8192}, K in {512,8192}, Nc=512).
// ---------------------------------------------------------------------------
__global__ void __launch_bounds__(256) sgemm_kernel(
    const float* __restrict__ A, const float* __restrict__ B,
    const float* __restrict__ bias, float* __restrict__ C,
    int M, int K, int Nc)
{
    __shared__ float As[16][128];
    __shared__ float Bs[16][64];

    const int tid = threadIdx.x;
    const int tx = tid & 15;       // 0..15 -> 4 cols each
    const int ty = tid >> 4;       // 0..15 -> 8 rows each
    const int blockRow = blockIdx.y * 128;
    const int blockCol = blockIdx.x * 64;

    float acc[8][4];
#pragma unroll
    for (int i = 0; i < 8; i++)
#pragma unroll
        for (int j = 0; j < 4; j++) acc[i][j] = 0.0f;

    for (int k0 = 0; k0 < K; k0 += 16) {
        // Load A tile: 128 rows x 16 cols = 512 float4, 2 per thread (coalesced)
#pragma unroll
        for (int l = 0; l < 2; ++l) {
            int idx = tid + l * 256;
            int row = idx >> 2;            // 0..127
            int kq  = (idx & 3) * 4;       // 0,4,8,12
            float4 v = *(const float4*)&A[(size_t)(blockRow + row) * K + k0 + kq];
            As[kq + 0][row] = v.x;
            As[kq + 1][row] = v.y;
            As[kq + 2][row] = v.z;
            As[kq + 3][row] = v.w;
        }
        // Load B tile: 16 rows x 64 cols = 256 float4, 1 per thread
        {
            int row = tid >> 4;            // 0..15
            int col = (tid & 15) * 4;      // 0..60
            *(float4*)&Bs[row][col] =
                *(const float4*)&B[(size_t)(k0 + row) * Nc + blockCol + col];
        }
        __syncthreads();

#pragma unroll
        for (int k = 0; k < 16; ++k) {
            float4 a0 = *(const float4*)&As[k][ty * 8];
            float4 a1 = *(const float4*)&As[k][ty * 8 + 4];
            float4 b0 = *(const float4*)&Bs[k][tx * 4];
            float a[8] = {a0.x, a0.y, a0.z, a0.w, a1.x, a1.y, a1.z, a1.w};
            float b[4] = {b0.x, b0.y, b0.z, b0.w};
#pragma unroll
            for (int i = 0; i < 8; i++)
#pragma unroll
                for (int j = 0; j < 4; j++)
                    acc[i][j] = fmaf(a[i], b[j], acc[i][j]);
        }
        __syncthreads();
    }

    const int cbase = blockCol + tx * 4;
    float4 bb = make_float4(0.f, 0.f, 0.f, 0.f);
    if (bias) bb = *(const float4*)&bias[cbase];
#pragma unroll
    for (int i = 0; i < 8; i++) {
        int r = blockRow + ty * 8 + i;
        float4 o;
        o.x = acc[i][0] + bb.x;
        o.y = acc[i][1] + bb.y;
        o.z = acc[i][2] + bb.z;
        o.w = acc[i][3] + bb.w;
        *(float4*)&C[(size_t)r * Nc + cbase] = o;
    }
}

// ---------------------------------------------------------------------------
// GCN aggregation (with PyG-style self loops + symmetric normalization)
// ---------------------------------------------------------------------------
// dest[n,f] = dinv[n]^2 * h[n,f]    (self-loop term, initializes dest fully)
__global__ void agg_self_kernel(const float* __restrict__ h, const float* __restrict__ dinv,
                                float* __restrict__ dest) {
    int i = blockIdx.x * blockDim.x + threadIdx.x;
    if (i < NF) {
        float dv = dinv[i >> 9];   // FDIM = 512
        dest[i] = dv * dv * h[i];
    }
}

// one block (128 threads) per edge, 4 feats per thread via float4 gather
__global__ void agg_edges_kernel(const float* __restrict__ h, float* __restrict__ dest,
                                 const int* __restrict__ src, const int* __restrict__ dst,
                                 const float* __restrict__ coef) {
    int e = blockIdx.x;
    int s = __ldg(&src[e]);
    int d = __ldg(&dst[e]);
    float c = __ldg(&coef[e]);
    int f = threadIdx.x * 4;
    float4 hv = *(const float4*)(h + (size_t)s * FDIM + f);
    float* dp = dest + (size_t)d * FDIM + f;
    atomicAdd(dp + 0, c * hv.x);
    atomicAdd(dp + 1, c * hv.y);
    atomicAdd(dp + 2, c * hv.z);
    atomicAdd(dp + 3, c * hv.w);
}

__global__ void relu_bias_kernel(float* __restrict__ x, const float* __restrict__ bias) {
    int i = blockIdx.x * blockDim.x + threadIdx.x;
    if (i < NF) x[i] = fmaxf(x[i] + bias[i & (FDIM - 1)], 0.0f);
}

// mp2 = relu(agg + b) + mp1   (agg already in out)
__global__ void mp2_final_kernel(float* __restrict__ out, const float* __restrict__ bias,
                                 const float* __restrict__ mp1) {
    int i = blockIdx.x * blockDim.x + threadIdx.x;
    if (i < NF) out[i] = fmaxf(out[i] + bias[i & (FDIM - 1)], 0.0f) + mp1[i];
}

// cross-stitch: 4 sequential 2x2 mixes composed into a single 2x2 matrix
__global__ void cs_kernel(float* __restrict__ yg, float* __restrict__ mp,
                          const float* __restrict__ cs) {
    float m00 = 1.f, m01 = 0.f, m10 = 0.f, m11 = 1.f;
#pragma unroll
    for (int i = 0; i < 4; i++) {
        float a = cs[i * 4 + 0], b = cs[i * 4 + 1];
        float c = cs[i * 4 + 2], d = cs[i * 4 + 3];
        float n00 = a * m00 + b * m10;
        float n01 = a * m01 + b * m11;
        float n10 = c * m00 + d * m10;
        float n11 = c * m01 + d * m11;
        m00 = n00; m01 = n01; m10 = n10; m11 = n11;
    }
    int i = blockIdx.x * blockDim.x + threadIdx.x;
    if (i < NF) {
        float y = yg[i], m = mp[i];
        yg[i] = m00 * y + m01 * m;
        mp[i] = m10 * y + m11 * m;
    }
}

// ---------------------------------------------------------------------------
// Channel attention
// ---------------------------------------------------------------------------
__global__ void poolsum_kernel(const float* __restrict__ x, int c) {
    float s = 0.0f;
    for (size_t i = (size_t)blockIdx.x * blockDim.x + threadIdx.x; i < (size_t)NF;
         i += (size_t)gridDim.x * blockDim.x)
        s += x[i];
#pragma unroll
    for (int o = 16; o > 0; o >>= 1) s += __shfl_down_sync(0xffffffffu, s, o);
    __shared__ float sm[8];
    if ((threadIdx.x & 31) == 0) sm[threadIdx.x >> 5] = s;
    __syncthreads();
    if (threadIdx.x < 8) {
        float v = sm[threadIdx.x];
#pragma unroll
        for (int o = 4; o > 0; o >>= 1) v += __shfl_down_sync(0xffu, v, o);
        if (threadIdx.x == 0) atomicAdd(&g_pooled[c], v);
    }
}

__global__ void att_kernel(const float* __restrict__ fc1W, const float* __restrict__ fc1b,
                           const float* __restrict__ fc2W, const float* __restrict__ fc2b) {
    if (threadIdx.x == 0 && blockIdx.x == 0) {
        float p[4];
#pragma unroll
        for (int c = 0; c < 4; c++) p[c] = g_pooled[c] * (1.0f / (float)NF);
        float hbuf[20];
        for (int j = 0; j < 20; j++) {
            float s = fc1b[j];
#pragma unroll
            for (int c = 0; c < 4; c++) s += p[c] * fc1W[c * 20 + j];
            hbuf[j] = fmaxf(s, 0.0f);
        }
        for (int c = 0; c < 4; c++) {
            float s = fc2b[c];
            for (int j = 0; j < 20; j++) s += hbuf[j] * fc2W[j * 4 + c];
            g_att[c] = 1.0f / (1.0f + expf(-s));
        }
    }
}

// out[n,f] = cnnb + sum_c cnnw[c] * relu(att[c] * Xc[n,f])
__global__ void combine_kernel(const float* __restrict__ x0, const float* __restrict__ x1,
                               const float* __restrict__ x2, const float* __restrict__ x3,
                               const float* __restrict__ cnnw, const float* __restrict__ cnnb,
                               float* __restrict__ out) {
    int i = blockIdx.x * blockDim.x + threadIdx.x;
    if (i < NF) {
        float r = cnnb[0];
        r += cnnw[0] * fmaxf(g_att[0] * x0[i], 0.0f);
        r += cnnw[1] * fmaxf(g_att[1] * x1[i], 0.0f);
        r += cnnw[2] * fmaxf(g_att[2] * x2[i], 0.0f);
        r += cnnw[3] * fmaxf(g_att[3] * x3[i], 0.0f);
        out[i] = r;
    }
}

// ---------------------------------------------------------------------------
// Host driver (graph-capturable: kernel launches only)
// ---------------------------------------------------------------------------
extern "C" void kernel_launch(void* const* d_in, const int* in_sizes, int n_in,
                              void* d_out, int out_size) {
    const float* x_d     = (const float*)d_in[0];
    const int*   edges_s = (const int*)  d_in[1];
    const float* w_s     = (const float*)d_in[2];
    const int*   edges_g = (const int*)  d_in[3];
    const float* w_g     = (const float*)d_in[4];
    const int*   edges_I = (const int*)  d_in[5];
    const float* reach   = (const float*)d_in[6];
    const float* W1s = (const float*)d_in[7],  *b1s = (const float*)d_in[8];
    const float* W2s = (const float*)d_in[9],  *b2s = (const float*)d_in[10];
    const float* W1g = (const float*)d_in[11], *b1g = (const float*)d_in[12];
    const float* W2g = (const float*)d_in[13], *b2g = (const float*)d_in[14];
    const float* WI1 = (const float*)d_in[15], *bI1 = (const float*)d_in[16];
    const float* WI2 = (const float*)d_in[17], *bI2 = (const float*)d_in[18];
    const float* fcW  = (const float*)d_in[19], *fcb  = (const float*)d_in[20];
    const float* cs   = (const float*)d_in[21];
    const float* fc1W = (const float*)d_in[22], *fc1b = (const float*)d_in[23];
    const float* fc2W = (const float*)d_in[24], *fc2b = (const float*)d_in[25];
    const float* cnnw = (const float*)d_in[26], *cnnb = (const float*)d_in[27];

    float* out_y   = (float*)d_out;          // y.T  [N, FD]
    float* out_mp2 = (float*)d_out + NF;     // mp2  [N, FD]

    float *feat, *h, *ys1, *yg1, *mp1, *ys2, *yg2;
    float *dinv_s, *dinv_g, *dinv_I, *coef_s, *coef_g, *coef_I, *pooled;
    cudaGetSymbolAddress((void**)&feat,   g_feat);
    cudaGetSymbolAddress((void**)&h,      g_h);
    cudaGetSymbolAddress((void**)&ys1,    g_ys1);
    cudaGetSymbolAddress((void**)&yg1,    g_yg1);
    cudaGetSymbolAddress((void**)&mp1,    g_mp1);
    cudaGetSymbolAddress((void**)&ys2,    g_ys2);
    cudaGetSymbolAddress((void**)&yg2,    g_yg2);
    cudaGetSymbolAddress((void**)&dinv_s, g_dinv_s);
    cudaGetSymbolAddress((void**)&dinv_g, g_dinv_g);
    cudaGetSymbolAddress((void**)&dinv_I, g_dinv_I);
    cudaGetSymbolAddress((void**)&coef_s, g_coef_s);
    cudaGetSymbolAddress((void**)&coef_g, g_coef_g);
    cudaGetSymbolAddress((void**)&coef_I, g_coef_I);
    cudaGetSymbolAddress((void**)&pooled, g_pooled);

    const int TB = 256;
    const int GN  = (NN + TB - 1) / TB;
    const int GE  = (NE + TB - 1) / TB;
    const int GF  = (NF + TB - 1) / TB;
    dim3 gemm_grid(FDIM / 64, NN / 128);

    // --- degree / normalization precompute (shared across both layers per edge set)
    fill_kernel<<<GN, TB>>>(dinv_s, 1.0f, NN);
    fill_kernel<<<GN, TB>>>(dinv_g, 1.0f, NN);
    fill_kernel<<<GN, TB>>>(dinv_I, 1.0f, NN);
    fill_kernel<<<1, 32>>>(pooled, 0.0f, 4);
    deg_kernel<<<GE, TB>>>(edges_s + NE, w_s,     dinv_s);
    deg_kernel<<<GE, TB>>>(edges_g + NE, w_g,     dinv_g);
    deg_kernel<<<GE, TB>>>(edges_I + NE, nullptr, dinv_I);
    rsqrt_kernel<<<GN, TB>>>(dinv_s, NN);
    rsqrt_kernel<<<GN, TB>>>(dinv_g, NN);
    rsqrt_kernel<<<GN, TB>>>(dinv_I, NN);
    coef_kernel<<<GE, TB>>>(edges_s, edges_s + NE, w_s,     dinv_s, coef_s);
    coef_kernel<<<GE, TB>>>(edges_g, edges_g + NE, w_g,     dinv_g, coef_g);
    coef_kernel<<<GE, TB>>>(edges_I, edges_I + NE, nullptr, dinv_I, coef_I);

    // --- feat = reach @ fcW + fcb   (the big GEMM)
    sgemm_kernel<<<gemm_grid, TB>>>(reach, fcW, fcb, feat, NN, NN, FDIM);

    // --- layer 1: y_s1 = relu(gcn(x_d, W1s))
    sgemm_kernel<<<gemm_grid, TB>>>(x_d, W1s, nullptr, h, NN, FDIM, FDIM);
    agg_self_kernel<<<GF, TB>>>(h, dinv_s, ys1);
    agg_edges_kernel<<<NE, FDIM / 4>>>(h, ys1, edges_s, edges_s + NE, coef_s);
    relu_bias_kernel<<<GF, TB>>>(ys1, b1s);

    // --- layer 1: y_g1 = relu(gcn(x_d, W1g))
    sgemm_kernel<<<gemm_grid, TB>>>(x_d, W1g, nullptr, h, NN, FDIM, FDIM);
    agg_self_kernel<<<GF, TB>>>(h, dinv_g, yg1);
    agg_edges_kernel<<<NE, FDIM / 4>>>(h, yg1, edges_g, edges_g + NE, coef_g);
    relu_bias_kernel<<<GF, TB>>>(yg1, b1g);

    // --- mp1 = relu(gcn(feat, WI1))
    sgemm_kernel<<<gemm_grid, TB>>>(feat, WI1, nullptr, h, NN, FDIM, FDIM);
    agg_self_kernel<<<GF, TB>>>(h, dinv_I, mp1);
    agg_edges_kernel<<<NE, FDIM / 4>>>(h, mp1, edges_I, edges_I + NE, coef_I);
    relu_bias_kernel<<<GF, TB>>>(mp1, bI1);

    // --- cross-stitch fusion (composed 2x2)
    cs_kernel<<<GF, TB>>>(yg1, mp1, cs);

    // --- layer 2: y_s2 = relu(gcn(y_s1, W2s))
    sgemm_kernel<<<gemm_grid, TB>>>(ys1, W2s, nullptr, h, NN, FDIM, FDIM);
    agg_self_kernel<<<GF, TB>>>(h, dinv_s, ys2);
    agg_edges_kernel<<<NE, FDIM / 4>>>(h, ys2, edges_s, edges_s + NE, coef_s);
    relu_bias_kernel<<<GF, TB>>>(ys2, b2s);

    // --- mp2 = relu(gcn(mp1, WI2)) + mp1  (straight to output)
    sgemm_kernel<<<gemm_grid, TB>>>(mp1, WI2, nullptr, h, NN, FDIM, FDIM);
    agg_self_kernel<<<GF, TB>>>(h, dinv_I, out_mp2);
    agg_edges_kernel<<<NE, FDIM / 4>>>(h, out_mp2, edges_I, edges_I + NE, coef_I);
    mp2_final_kernel<<<GF, TB>>>(out_mp2, bI2, mp1);

    // --- layer 2: y_g2 = relu(gcn(y_g1, W2g))
    sgemm_kernel<<<gemm_grid, TB>>>(yg1, W2g, nullptr, h, NN, FDIM, FDIM);
    agg_self_kernel<<<GF, TB>>>(h, dinv_g, yg2);
    agg_edges_kernel<<<NE, FDIM / 4>>>(h, yg2, edges_g, edges_g + NE, coef_g);
    relu_bias_kernel<<<GF, TB>>>(yg2, b2g);

    // --- channel attention + 1x1 conv combine
    poolsum_kernel<<<512, TB>>>(ys1, 0);
    poolsum_kernel<<<512, TB>>>(ys2, 1);
    poolsum_kernel<<<512, TB>>>(yg1, 2);
    poolsum_kernel<<<512, TB>>>(yg2, 3);
    att_kernel<<<1, 32>>>(fc1W, fc1b, fc2W, fc2b);
    combine_kernel<<<GF, TB>>>(ys1, ys2, yg1, yg2, cnnw, cnnb, out_y);
}

// round 16
// speedup vs baseline: 2.7799x; 2.7799x over previous
#include <cuda_runtime.h>
#include <cuda_bf16.h>
#include <math.h>
#include <stdint.h>

#define NN   8192
#define FDIM 512
#define NEDGE 262144
#define NF   (NN * FDIM)   // 4194304

// ---------------------------------------------------------------------------
// Static device scratch
// ---------------------------------------------------------------------------
__device__ float g_feat[NF];
__device__ float g_h[NF];
__device__ float g_ys1[NF];
__device__ float g_yg1[NF];
__device__ float g_mp1[NF];
__device__ float g_ys2[NF];
__device__ float g_yg2[NF];
__device__ float g_dinv[3][NN];
__device__ float g_coef[3][NEDGE];
__device__ float g_pooled[4];
__device__ float g_att[4];

// CSR (dst-sorted) edge storage, one set per edge list
__device__ int   g_rowptr[3][NN + 1];
__device__ int   g_fillc[3][NN];
__device__ int   g_esrc[3][NEDGE];
__device__ float g_ecoef[3][NEDGE];

// bf16 split buffers
__device__ __nv_bfloat16 g_Rhi[NN * NN];        // reach hi   (128 MB)
__device__ __nv_bfloat16 g_Rlo[NN * NN];        // reach lo   (128 MB)
__device__ __nv_bfloat16 g_Fhi[FDIM * NN];      // fcW^T hi   [512, 8192]
__device__ __nv_bfloat16 g_Flo[FDIM * NN];      // fcW^T lo
__device__ __nv_bfloat16 g_Wthi[6][FDIM * FDIM];// W^T hi     [512, 512] x6
__device__ __nv_bfloat16 g_Wtlo[6][FDIM * FDIM];
__device__ __nv_bfloat16 g_Ahi[NF];             // A-operand split (reused)
__device__ __nv_bfloat16 g_Alo[NF];

// ---------------------------------------------------------------------------
// PTX helpers (sm_80+-compatible only; compute_103 virtual arch rejects
// tcgen05/TMEM, so the GEMM uses warp-level mma.sync HMMA instead)
// ---------------------------------------------------------------------------
__device__ __forceinline__ uint32_t smem_u32(const void* p) {
    uint32_t a;
    asm("{ .reg .u64 t; cvta.to.shared.u64 t, %1; cvt.u32.u64 %0, t; }" : "=r"(a) : "l"(p));
    return a;
}
__device__ __forceinline__ void cp16(uint32_t d, const void* s) {
    asm volatile("cp.async.cg.shared.global [%0], [%1], 16;" :: "r"(d), "l"(s));
}
__device__ __forceinline__ void cp_commit() { asm volatile("cp.async.commit_group;"); }
template <int NPEND> __device__ __forceinline__ void cp_wait() {
    asm volatile("cp.async.wait_group %0;" :: "n"(NPEND));
}
__device__ __forceinline__ void ldsm_x4(uint32_t* r, uint32_t addr) {
    asm volatile("ldmatrix.sync.aligned.m8n8.x4.shared.b16 {%0,%1,%2,%3}, [%4];"
                 : "=r"(r[0]), "=r"(r[1]), "=r"(r[2]), "=r"(r[3]) : "r"(addr));
}
__device__ __forceinline__ void mma16816(float* d, const uint32_t* a, uint32_t b0, uint32_t b1) {
    asm volatile("mma.sync.aligned.m16n8k16.row.col.f32.bf16.bf16.f32 "
                 "{%0,%1,%2,%3}, {%4,%5,%6,%7}, {%8,%9}, {%0,%1,%2,%3};"
                 : "+f"(d[0]), "+f"(d[1]), "+f"(d[2]), "+f"(d[3])
                 : "r"(a[0]), "r"(a[1]), "r"(a[2]), "r"(a[3]), "r"(b0), "r"(b1));
}

// ---------------------------------------------------------------------------
// HMMA GEMM: C[M,512] = A[M,K] * B[K,512] fp32 via bf16 hi/lo split.
// A row-major hi/lo [M,K]; B pre-transposed K-major hi/lo [512,K].
// 3 passes: Ahi*Bhi + Ahi*Blo + Alo*Bhi, accumulated in fp32 registers.
// CTA tile 128x128, 8 warps (4x2), warp tile 32x64 (2x8 m16n8 frags).
// K-chunk 64, cp.async double buffer, padded smem rows (144B) for
// conflict-free ldmatrix.
// ---------------------------------------------------------------------------
#define GKC 64
#define LDAB 144                      // smem row stride bytes (72 bf16)
#define TILE_BYTES (128 * LDAB)       // 18432
#define STAGE_BYTES (2 * TILE_BYTES)  // A + B per stage = 36864
#define GEMM_SMEM (2 * STAGE_BYTES)   // double buffer = 73728

__global__ void __launch_bounds__(256, 2) mma_gemm_kernel(
    const __nv_bfloat16* __restrict__ Ahi, const __nv_bfloat16* __restrict__ Alo,
    const __nv_bfloat16* __restrict__ Bhi, const __nv_bfloat16* __restrict__ Blo,
    const float* __restrict__ bias, float* __restrict__ C, int K)
{
    extern __shared__ char smem[];
    const int tid   = threadIdx.x;
    const int wid   = tid >> 5;
    const int lane  = tid & 31;
    const int warpM = wid >> 1;      // 0..3 -> 32 rows each
    const int warpN = wid & 1;       // 0..1 -> 64 cols each
    const uint32_t sbase = smem_u32(smem);
    const int tileM = blockIdx.y * 128;
    const int tileN = blockIdx.x * 128;
    const int NC  = K / GKC;
    const int TOT = 3 * NC;

    const __nv_bfloat16* APASS[3] = {Ahi, Ahi, Alo};
    const __nv_bfloat16* BPASS[3] = {Bhi, Blo, Bhi};

    float acc[2][8][4];
#pragma unroll
    for (int mt = 0; mt < 2; mt++)
#pragma unroll
        for (int nt = 0; nt < 8; nt++)
#pragma unroll
            for (int q = 0; q < 4; q++) acc[mt][nt][q] = 0.0f;

    auto do_load = [&](int chunk, int stage) {
        int pass = chunk / NC;
        int ck   = chunk - pass * NC;
        const __nv_bfloat16* Ap = APASS[pass] + (size_t)tileM * K + ck * GKC;
        const __nv_bfloat16* Bp = BPASS[pass] + (size_t)tileN * K + ck * GKC;
        uint32_t sA = sbase + stage * STAGE_BYTES;
        uint32_t sB = sA + TILE_BYTES;
#pragma unroll
        for (int l = 0; l < 4; l++) {           // 128 rows x 4 x 16B = A tile
            int idx = tid + 256 * l;
            int r = idx >> 3, c = idx & 7;
            cp16(sA + r * LDAB + c * 16, Ap + (size_t)r * K + c * 8);
        }
#pragma unroll
        for (int l = 0; l < 4; l++) {
            int idx = tid + 256 * l;
            int r = idx >> 3, c = idx & 7;
            cp16(sB + r * LDAB + c * 16, Bp + (size_t)r * K + c * 8);
        }
    };

    do_load(0, 0); cp_commit();

    for (int chunk = 0; chunk < TOT; ++chunk) {
        if (chunk + 1 < TOT) { do_load(chunk + 1, (chunk + 1) & 1); cp_commit(); cp_wait<1>(); }
        else                 cp_wait<0>();
        __syncthreads();
        uint32_t sA = sbase + (chunk & 1) * STAGE_BYTES;
        uint32_t sB = sA + TILE_BYTES;
#pragma unroll
        for (int k16 = 0; k16 < 4; ++k16) {
            int k_off = k16 * 16;
            uint32_t a[2][4];
#pragma unroll
            for (int mt = 0; mt < 2; mt++) {
                int m_base = warpM * 32 + mt * 16;
                int row = m_base + (lane & 7) + ((lane & 8) ? 8 : 0);
                int kk  = k_off + ((lane & 16) ? 8 : 0);
                ldsm_x4(a[mt], sA + row * LDAB + kk * 2);
            }
            uint32_t b[4][4];    // each x4 covers two adjacent n-tiles
#pragma unroll
            for (int np = 0; np < 4; np++) {
                int n_base = warpN * 64 + np * 16;
                int nrow = n_base + (lane & 7) + ((lane & 16) ? 8 : 0);
                int kk   = k_off + ((lane & 8) ? 8 : 0);
                ldsm_x4(b[np], sB + nrow * LDAB + kk * 2);
            }
#pragma unroll
            for (int mt = 0; mt < 2; mt++)
#pragma unroll
                for (int nt = 0; nt < 8; nt++)
                    mma16816(acc[mt][nt], a[mt],
                             b[nt >> 1][(nt & 1) * 2 + 0],
                             b[nt >> 1][(nt & 1) * 2 + 1]);
        }
        __syncthreads();
    }

    // epilogue: c0,c1 = (m, n/n+1); c2,c3 = (m+8, n/n+1)
#pragma unroll
    for (int mt = 0; mt < 2; mt++) {
        int m0 = tileM + warpM * 32 + mt * 16 + (lane >> 2);
#pragma unroll
        for (int nt = 0; nt < 8; nt++) {
            int n0 = tileN + warpN * 64 + nt * 8 + (lane & 3) * 2;
            float bx = 0.0f, by = 0.0f;
            if (bias) { bx = bias[n0]; by = bias[n0 + 1]; }
            float2 v0 = make_float2(acc[mt][nt][0] + bx, acc[mt][nt][1] + by);
            float2 v1 = make_float2(acc[mt][nt][2] + bx, acc[mt][nt][3] + by);
            *(float2*)&C[(size_t)m0 * FDIM + n0]       = v0;
            *(float2*)&C[(size_t)(m0 + 8) * FDIM + n0] = v1;
        }
    }
}

// ---------------------------------------------------------------------------
// split / transpose-split kernels
// ---------------------------------------------------------------------------
__global__ void split_kernel(const float* __restrict__ x,
                             __nv_bfloat16* __restrict__ hi,
                             __nv_bfloat16* __restrict__ lo, int n) {
    int i = blockIdx.x * blockDim.x + threadIdx.x;
    if (i < n) {
        float v = x[i];
        __nv_bfloat16 h = __float2bfloat16(v);
        hi[i] = h;
        lo[i] = __float2bfloat16(v - __bfloat162float(h));
    }
}

__global__ void tsplit_kernel(const float* __restrict__ W,
                              __nv_bfloat16* __restrict__ hi,
                              __nv_bfloat16* __restrict__ lo, int K, int Nc) {
    int i = blockIdx.x * blockDim.x + threadIdx.x;
    if (i < K * Nc) {
        int n = i / K, k = i - n * K;
        float v = W[(size_t)k * Nc + n];
        __nv_bfloat16 h = __float2bfloat16(v);
        hi[i] = h;
        lo[i] = __float2bfloat16(v - __bfloat162float(h));
    }
}

// ---------------------------------------------------------------------------
// Degree / coef / CSR build
// ---------------------------------------------------------------------------
__global__ void fill_kernel(float* p, float v, int n) {
    int i = blockIdx.x * blockDim.x + threadIdx.x;
    if (i < n) p[i] = v;
}
__global__ void zeroi_kernel(int* p, int n) {
    int i = blockIdx.x * blockDim.x + threadIdx.x;
    if (i < n) p[i] = 0;
}

__global__ void deg_kernel(const int* __restrict__ dst, const float* __restrict__ w,
                           float* __restrict__ deg) {
    int e = blockIdx.x * blockDim.x + threadIdx.x;
    if (e < NEDGE) atomicAdd(&deg[dst[e]], w ? w[e] : 1.0f);
}

__global__ void rsqrt_kernel(float* p, int n) {
    int i = blockIdx.x * blockDim.x + threadIdx.x;
    if (i < n) p[i] = rsqrtf(p[i]);
}

__global__ void coef_kernel(const int* __restrict__ src, const int* __restrict__ dst,
                            const float* __restrict__ w, const float* __restrict__ dinv,
                            float* __restrict__ coef) {
    int e = blockIdx.x * blockDim.x + threadIdx.x;
    if (e < NEDGE) coef[e] = dinv[src[e]] * (w ? w[e] : 1.0f) * dinv[dst[e]];
}

__global__ void count_kernel(const int* __restrict__ dst, int* __restrict__ cnt) {
    int e = blockIdx.x * blockDim.x + threadIdx.x;
    if (e < NEDGE) atomicAdd(&cnt[dst[e]], 1);
}

// exclusive prefix over 8192 counts -> rowptr[0..8192]; 1 block x 1024 threads
__global__ void __launch_bounds__(1024) scan_kernel(const int* __restrict__ cnt,
                                                    int* __restrict__ rowptr) {
    __shared__ int sh[1024];
    int t = threadIdx.x;
    int base = t * 8;
    int loc[8];
    int sum = 0;
#pragma unroll
    for (int i = 0; i < 8; i++) { sum += cnt[base + i]; loc[i] = sum; }  // inclusive local
    sh[t] = sum;
    __syncthreads();
    for (int off = 1; off < 1024; off <<= 1) {
        int v = (t >= off) ? sh[t - off] : 0;
        __syncthreads();
        sh[t] += v;
        __syncthreads();
    }
    int offset = (t == 0) ? 0 : sh[t - 1];
#pragma unroll
    for (int i = 0; i < 8; i++) rowptr[base + i + 1] = offset + loc[i];
    if (t == 0) rowptr[0] = 0;
}

__global__ void scatter_kernel(const int* __restrict__ src, const int* __restrict__ dst,
                               const float* __restrict__ coef,
                               const int* __restrict__ rowptr, int* __restrict__ fillc,
                               int* __restrict__ esrc, float* __restrict__ ecoef) {
    int e = blockIdx.x * blockDim.x + threadIdx.x;
    if (e < NEDGE) {
        int d = dst[e];
        int pos = rowptr[d] + atomicAdd(&fillc[d], 1);
        esrc[pos]  = src[e];
        ecoef[pos] = coef[e];
    }
}

// ---------------------------------------------------------------------------
// CSR GCN aggregation: one block per dst node, 128 threads (4 floats each).
// dest[d] = dinv[d]^2 * h[d] + sum_edges coef * h[src]
// ---------------------------------------------------------------------------
__global__ void __launch_bounds__(128) agg_csr_kernel(
    const float* __restrict__ h, const float* __restrict__ dinv,
    const int* __restrict__ rowptr, const int* __restrict__ esrc,
    const float* __restrict__ ecoef, float* __restrict__ dest)
{
    int d = blockIdx.x;
    int f = threadIdx.x * 4;
    float dv = dinv[d];
    float4 acc = *(const float4*)(h + (size_t)d * FDIM + f);
    acc.x *= dv * dv; acc.y *= dv * dv; acc.z *= dv * dv; acc.w *= dv * dv;
    int p0 = __ldg(&rowptr[d]), p1 = __ldg(&rowptr[d + 1]);
    for (int p = p0; p < p1; ++p) {
        int s = __ldg(&esrc[p]);
        float c = __ldg(&ecoef[p]);
        float4 hv = *(const float4*)(h + (size_t)s * FDIM + f);
        acc.x = fmaf(c, hv.x, acc.x);
        acc.y = fmaf(c, hv.y, acc.y);
        acc.z = fmaf(c, hv.z, acc.z);
        acc.w = fmaf(c, hv.w, acc.w);
    }
    *(float4*)(dest + (size_t)d * FDIM + f) = acc;
}

__global__ void relu_bias_kernel(float* __restrict__ x, const float* __restrict__ bias) {
    int i = blockIdx.x * blockDim.x + threadIdx.x;
    if (i < NF) x[i] = fmaxf(x[i] + bias[i & (FDIM - 1)], 0.0f);
}

__global__ void mp2_final_kernel(float* __restrict__ out, const float* __restrict__ bias,
                                 const float* __restrict__ mp1) {
    int i = blockIdx.x * blockDim.x + threadIdx.x;
    if (i < NF) out[i] = fmaxf(out[i] + bias[i & (FDIM - 1)], 0.0f) + mp1[i];
}

__global__ void cs_kernel(float* __restrict__ yg, float* __restrict__ mp,
                          const float* __restrict__ cs) {
    float m00 = 1.f, m01 = 0.f, m10 = 0.f, m11 = 1.f;
#pragma unroll
    for (int i = 0; i < 4; i++) {
        float a = cs[i * 4 + 0], b = cs[i * 4 + 1];
        float c = cs[i * 4 + 2], d = cs[i * 4 + 3];
        float n00 = a * m00 + b * m10, n01 = a * m01 + b * m11;
        float n10 = c * m00 + d * m10, n11 = c * m01 + d * m11;
        m00 = n00; m01 = n01; m10 = n10; m11 = n11;
    }
    int i = blockIdx.x * blockDim.x + threadIdx.x;
    if (i < NF) {
        float y = yg[i], m = mp[i];
        yg[i] = m00 * y + m01 * m;
        mp[i] = m10 * y + m11 * m;
    }
}

// ---------------------------------------------------------------------------
// Channel attention
// ---------------------------------------------------------------------------
__global__ void poolsum_kernel(const float* __restrict__ x, int c) {
    float s = 0.0f;
    for (size_t i = (size_t)blockIdx.x * blockDim.x + threadIdx.x; i < (size_t)NF;
         i += (size_t)gridDim.x * blockDim.x)
        s += x[i];
#pragma unroll
    for (int o = 16; o > 0; o >>= 1) s += __shfl_down_sync(0xffffffffu, s, o);
    __shared__ float sm[8];
    if ((threadIdx.x & 31) == 0) sm[threadIdx.x >> 5] = s;
    __syncthreads();
    if (threadIdx.x < 8) {
        float v = sm[threadIdx.x];
#pragma unroll
        for (int o = 4; o > 0; o >>= 1) v += __shfl_down_sync(0xffu, v, o);
        if (threadIdx.x == 0) atomicAdd(&g_pooled[c], v);
    }
}

__global__ void att_kernel(const float* __restrict__ fc1W, const float* __restrict__ fc1b,
                           const float* __restrict__ fc2W, const float* __restrict__ fc2b) {
    if (threadIdx.x == 0 && blockIdx.x == 0) {
        float p[4];
#pragma unroll
        for (int c = 0; c < 4; c++) p[c] = g_pooled[c] * (1.0f / (float)NF);
        float hbuf[20];
        for (int j = 0; j < 20; j++) {
            float s = fc1b[j];
#pragma unroll
            for (int c = 0; c < 4; c++) s += p[c] * fc1W[c * 20 + j];
            hbuf[j] = fmaxf(s, 0.0f);
        }
        for (int c = 0; c < 4; c++) {
            float s = fc2b[c];
            for (int j = 0; j < 20; j++) s += hbuf[j] * fc2W[j * 4 + c];
            g_att[c] = 1.0f / (1.0f + expf(-s));
        }
    }
}

__global__ void combine_kernel(const float* __restrict__ x0, const float* __restrict__ x1,
                               const float* __restrict__ x2, const float* __restrict__ x3,
                               const float* __restrict__ cnnw, const float* __restrict__ cnnb,
                               float* __restrict__ out) {
    int i = blockIdx.x * blockDim.x + threadIdx.x;
    if (i < NF) {
        float r = cnnb[0];
        r += cnnw[0] * fmaxf(g_att[0] * x0[i], 0.0f);
        r += cnnw[1] * fmaxf(g_att[1] * x1[i], 0.0f);
        r += cnnw[2] * fmaxf(g_att[2] * x2[i], 0.0f);
        r += cnnw[3] * fmaxf(g_att[3] * x3[i], 0.0f);
        out[i] = r;
    }
}

// ---------------------------------------------------------------------------
// Host driver
// ---------------------------------------------------------------------------
extern "C" void kernel_launch(void* const* d_in, const int* in_sizes, int n_in,
                              void* d_out, int out_size) {
    const float* x_d     = (const float*)d_in[0];
    const int*   edges_s = (const int*)  d_in[1];
    const float* w_s     = (const float*)d_in[2];
    const int*   edges_g = (const int*)  d_in[3];
    const float* w_g     = (const float*)d_in[4];
    const int*   edges_I = (const int*)  d_in[5];
    const float* reach   = (const float*)d_in[6];
    const float* W1s = (const float*)d_in[7],  *b1s = (const float*)d_in[8];
    const float* W2s = (const float*)d_in[9],  *b2s = (const float*)d_in[10];
    const float* W1g = (const float*)d_in[11], *b1g = (const float*)d_in[12];
    const float* W2g = (const float*)d_in[13], *b2g = (const float*)d_in[14];
    const float* WI1 = (const float*)d_in[15], *bI1 = (const float*)d_in[16];
    const float* WI2 = (const float*)d_in[17], *bI2 = (const float*)d_in[18];
    const float* fcW  = (const float*)d_in[19], *fcb  = (const float*)d_in[20];
    const float* cs   = (const float*)d_in[21];
    const float* fc1W = (const float*)d_in[22], *fc1b = (const float*)d_in[23];
    const float* fc2W = (const float*)d_in[24], *fc2b = (const float*)d_in[25];
    const float* cnnw = (const float*)d_in[26], *cnnb = (const float*)d_in[27];

    float* out_y   = (float*)d_out;
    float* out_mp2 = (float*)d_out + NF;

    float *feat, *h, *ys1, *yg1, *mp1, *ys2, *yg2, *dinv, *coefp, *pooled;
    int *rowptr, *fillc, *esrc;
    float *ecoef;
    __nv_bfloat16 *Rhi, *Rlo, *Fhi, *Flo, *Ahi, *Alo, *Wthi, *Wtlo;
    cudaGetSymbolAddress((void**)&feat,   g_feat);
    cudaGetSymbolAddress((void**)&h,      g_h);
    cudaGetSymbolAddress((void**)&ys1,    g_ys1);
    cudaGetSymbolAddress((void**)&yg1,    g_yg1);
    cudaGetSymbolAddress((void**)&mp1,    g_mp1);
    cudaGetSymbolAddress((void**)&ys2,    g_ys2);
    cudaGetSymbolAddress((void**)&yg2,    g_yg2);
    cudaGetSymbolAddress((void**)&dinv,   g_dinv);
    cudaGetSymbolAddress((void**)&coefp,  g_coef);
    cudaGetSymbolAddress((void**)&pooled, g_pooled);
    cudaGetSymbolAddress((void**)&rowptr, g_rowptr);
    cudaGetSymbolAddress((void**)&fillc,  g_fillc);
    cudaGetSymbolAddress((void**)&esrc,   g_esrc);
    cudaGetSymbolAddress((void**)&ecoef,  g_ecoef);
    cudaGetSymbolAddress((void**)&Rhi,    g_Rhi);
    cudaGetSymbolAddress((void**)&Rlo,    g_Rlo);
    cudaGetSymbolAddress((void**)&Fhi,    g_Fhi);
    cudaGetSymbolAddress((void**)&Flo,    g_Flo);
    cudaGetSymbolAddress((void**)&Ahi,    g_Ahi);
    cudaGetSymbolAddress((void**)&Alo,    g_Alo);
    cudaGetSymbolAddress((void**)&Wthi,   g_Wthi);
    cudaGetSymbolAddress((void**)&Wtlo,   g_Wtlo);

    cudaFuncSetAttribute(mma_gemm_kernel, cudaFuncAttributeMaxDynamicSharedMemorySize, GEMM_SMEM);

    const int TB = 256;
    const int GN = (NN + TB - 1) / TB;
    const int GE = (NEDGE + TB - 1) / TB;
    const int GF = (NF + TB - 1) / TB;
    dim3 ggrid(FDIM / 128, NN / 128);   // (4, 64)
    const int WSZ = FDIM * FDIM;

    const int* EDGES[3] = {edges_s, edges_g, edges_I};
    const float* WEI[3] = {w_s, w_g, nullptr};

    // --- per-edge-set: degree, coef, CSR build
    fill_kernel<<<1, 32>>>(pooled, 0.0f, 4);
    for (int k = 0; k < 3; k++) {
        float* dv = dinv + k * NN;
        float* cf = coefp + k * NEDGE;
        int*   rp = rowptr + k * (NN + 1);
        int*   fc = fillc + k * NN;
        int*   es = esrc + k * NEDGE;
        float* ec = ecoef + k * NEDGE;
        const int* src = EDGES[k];
        const int* dst = EDGES[k] + NEDGE;

        fill_kernel<<<GN, TB>>>(dv, 1.0f, NN);
        deg_kernel<<<GE, TB>>>(dst, WEI[k], dv);
        rsqrt_kernel<<<GN, TB>>>(dv, NN);
        coef_kernel<<<GE, TB>>>(src, dst, WEI[k], dv, cf);
        zeroi_kernel<<<GN, TB>>>(fc, NN);
        count_kernel<<<GE, TB>>>(dst, fc);
        scan_kernel<<<1, 1024>>>(fc, rp);
        zeroi_kernel<<<GN, TB>>>(fc, NN);
        scatter_kernel<<<GE, TB>>>(src, dst, cf, rp, fc, es, ec);
    }
    int*   rp_s = rowptr + 0 * (NN + 1), *rp_g = rowptr + 1 * (NN + 1), *rp_I = rowptr + 2 * (NN + 1);
    int*   es_s = esrc + 0 * NEDGE, *es_g = esrc + 1 * NEDGE, *es_I = esrc + 2 * NEDGE;
    float* ec_s = ecoef + 0 * NEDGE, *ec_g = ecoef + 1 * NEDGE, *ec_I = ecoef + 2 * NEDGE;
    float* dv_s = dinv + 0 * NN, *dv_g = dinv + 1 * NN, *dv_I = dinv + 2 * NN;

    // --- bf16 splits / transposed weight splits
    split_kernel<<<NN * NN / TB, TB>>>(reach, Rhi, Rlo, NN * NN);
    tsplit_kernel<<<(NN * FDIM) / TB, TB>>>(fcW, Fhi, Flo, NN, FDIM);   // [512, 8192]
    tsplit_kernel<<<WSZ / TB, TB>>>(W1s, Wthi + 0 * WSZ, Wtlo + 0 * WSZ, FDIM, FDIM);
    tsplit_kernel<<<WSZ / TB, TB>>>(W2s, Wthi + 1 * WSZ, Wtlo + 1 * WSZ, FDIM, FDIM);
    tsplit_kernel<<<WSZ / TB, TB>>>(W1g, Wthi + 2 * WSZ, Wtlo + 2 * WSZ, FDIM, FDIM);
    tsplit_kernel<<<WSZ / TB, TB>>>(W2g, Wthi + 3 * WSZ, Wtlo + 3 * WSZ, FDIM, FDIM);
    tsplit_kernel<<<WSZ / TB, TB>>>(WI1, Wthi + 4 * WSZ, Wtlo + 4 * WSZ, FDIM, FDIM);
    tsplit_kernel<<<WSZ / TB, TB>>>(WI2, Wthi + 5 * WSZ, Wtlo + 5 * WSZ, FDIM, FDIM);
    split_kernel<<<GF, TB>>>(x_d, Ahi, Alo, NF);

    // --- feat = reach @ fcW + fcb  (K = 8192)
    mma_gemm_kernel<<<ggrid, 256, GEMM_SMEM>>>(Rhi, Rlo, Fhi, Flo, fcb, feat, NN);

    // --- layer 1: y_s1
    mma_gemm_kernel<<<ggrid, 256, GEMM_SMEM>>>(Ahi, Alo, Wthi + 0 * WSZ, Wtlo + 0 * WSZ, nullptr, h, FDIM);
    agg_csr_kernel<<<NN, 128>>>(h, dv_s, rp_s, es_s, ec_s, ys1);
    relu_bias_kernel<<<GF, TB>>>(ys1, b1s);

    // --- layer 1: y_g1
    mma_gemm_kernel<<<ggrid, 256, GEMM_SMEM>>>(Ahi, Alo, Wthi + 2 * WSZ, Wtlo + 2 * WSZ, nullptr, h, FDIM);
    agg_csr_kernel<<<NN, 128>>>(h, dv_g, rp_g, es_g, ec_g, yg1);
    relu_bias_kernel<<<GF, TB>>>(yg1, b1g);

    // --- mp1 = relu(gcn(feat, WI1))
    split_kernel<<<GF, TB>>>(feat, Ahi, Alo, NF);
    mma_gemm_kernel<<<ggrid, 256, GEMM_SMEM>>>(Ahi, Alo, Wthi + 4 * WSZ, Wtlo + 4 * WSZ, nullptr, h, FDIM);
    agg_csr_kernel<<<NN, 128>>>(h, dv_I, rp_I, es_I, ec_I, mp1);
    relu_bias_kernel<<<GF, TB>>>(mp1, bI1);

    // --- cross-stitch
    cs_kernel<<<GF, TB>>>(yg1, mp1, cs);

    // --- layer 2: y_s2
    split_kernel<<<GF, TB>>>(ys1, Ahi, Alo, NF);
    mma_gemm_kernel<<<ggrid, 256, GEMM_SMEM>>>(Ahi, Alo, Wthi + 1 * WSZ, Wtlo + 1 * WSZ, nullptr, h, FDIM);
    agg_csr_kernel<<<NN, 128>>>(h, dv_s, rp_s, es_s, ec_s, ys2);
    relu_bias_kernel<<<GF, TB>>>(ys2, b2s);

    // --- mp2 = relu(gcn(mp1, WI2)) + mp1  (to output)
    split_kernel<<<GF, TB>>>(mp1, Ahi, Alo, NF);
    mma_gemm_kernel<<<ggrid, 256, GEMM_SMEM>>>(Ahi, Alo, Wthi + 5 * WSZ, Wtlo + 5 * WSZ, nullptr, h, FDIM);
    agg_csr_kernel<<<NN, 128>>>(h, dv_I, rp_I, es_I, ec_I, out_mp2);
    mp2_final_kernel<<<GF, TB>>>(out_mp2, bI2, mp1);

    // --- layer 2: y_g2
    split_kernel<<<GF, TB>>>(yg1, Ahi, Alo, NF);
    mma_gemm_kernel<<<ggrid, 256, GEMM_SMEM>>>(Ahi, Alo, Wthi + 3 * WSZ, Wtlo + 3 * WSZ, nullptr, h, FDIM);
    agg_csr_kernel<<<NN, 128>>>(h, dv_g, rp_g, es_g, ec_g, yg2);
    relu_bias_kernel<<<GF, TB>>>(yg2, b2g);

    // --- channel attention + combine
    poolsum_kernel<<<512, TB>>>(ys1, 0);
    poolsum_kernel<<<512, TB>>>(ys2, 1);
    poolsum_kernel<<<512, TB>>>(yg1, 2);
    poolsum_kernel<<<512, TB>>>(yg2, 3);
    att_kernel<<<1, 32>>>(fc1W, fc1b, fc2W, fc2b);
    combine_kernel<<<GF, TB>>>(ys1, ys2, yg1, yg2, cnnw, cnnb, out_y);
}